// round 7
// baseline (speedup 1.0000x reference)
#include <cuda_runtime.h>

// Grid_nd_sample: bilinear gather, point-sorted for DRAM page locality.
// in_tensor: (B=16, H=128, W=128, C=256) fp32 (268 MB)
// indices:   (B, P=8192, 2) fp32
// out:       (B, P, C) fp32 (134 MB)
//
// Pipeline: zero -> histogram(b,y) -> scan(2048) -> scatter -> gather kernel
// processing points in (b, y0)-sorted order. Consecutive points touch rows in
// a small contiguous region -> DRAM page hits + L2 dedup of shared rows.

namespace {
constexpr int B = 16;
constexpr int H = 128;
constexpr int W = 128;
constexpr int C = 256;
constexpr int P = 8192;
constexpr int NPTS = B * P;                 // 131072
constexpr int NBKT = B * H;                 // 2048 buckets
constexpr int C4 = C / 4;                   // 64 float4 chunks per point
constexpr long NPAIR = (long)NPTS / 2;      // 65536
constexpr long TOTAL = NPAIR * C4;          // 4,194,304 threads
}

__device__ int g_cnt[NBKT];
__device__ int g_cursor[NBKT];
__device__ int g_order[NPTS];

__global__ void zero_kernel() {
    int i = blockIdx.x * blockDim.x + threadIdx.x;
    if (i < NBKT) { g_cnt[i] = 0; }
}

__global__ void hist_kernel(const float* __restrict__ idx) {
    int p = blockIdx.x * blockDim.x + threadIdx.x;
    if (p >= NPTS) return;
    int b = p >> 13;
    int y = (int)floorf(idx[(long)p * 2]);
    y = min(max(y, 0), H - 1);
    atomicAdd(&g_cnt[b * H + y], 1);
}

// Single-block inclusive scan over 2048 counters -> exclusive bases in g_cursor
__global__ void scan_kernel() {
    __shared__ int sh[NBKT];
    int t = threadIdx.x;                 // 1024 threads, 2 elems each
    sh[t] = g_cnt[t];
    sh[t + 1024] = g_cnt[t + 1024];
    __syncthreads();
    // Hillis-Steele inclusive scan (double-buffer in place with temp)
    for (int off = 1; off < NBKT; off <<= 1) {
        int a0 = (t        >= off) ? sh[t        - off] : 0;
        int a1 = (t + 1024 >= off) ? sh[t + 1024 - off] : 0;
        __syncthreads();
        sh[t] += a0;
        sh[t + 1024] += a1;
        __syncthreads();
    }
    g_cursor[t]        = sh[t]        - g_cnt[t];         // exclusive
    g_cursor[t + 1024] = sh[t + 1024] - g_cnt[t + 1024];
}

__global__ void scatter_kernel(const float* __restrict__ idx) {
    int p = blockIdx.x * blockDim.x + threadIdx.x;
    if (p >= NPTS) return;
    int b = p >> 13;
    int y = (int)floorf(idx[(long)p * 2]);
    y = min(max(y, 0), H - 1);
    int pos = atomicAdd(&g_cursor[b * H + y], 1);
    g_order[pos] = p;
}

__global__ __launch_bounds__(256) void grid_sample_kernel(
    const float* __restrict__ in,
    const float* __restrict__ idx,
    float* __restrict__ out)
{
    long i = (long)blockIdx.x * blockDim.x + threadIdx.x;
    if (i >= TOTAL) return;

    int  c4   = (int)(i & (C4 - 1));   // 0..63
    long pair = i >> 6;

    // Sorted point ids (warp-uniform loads -> broadcast)
    int s0 = __ldg(&g_order[pair * 2 + 0]);
    int s1 = __ldg(&g_order[pair * 2 + 1]);
    int b0 = s0 >> 13;
    int b1 = s1 >> 13;

    float iy0 = __ldg(&idx[(long)s0 * 2 + 0]);
    float ix0 = __ldg(&idx[(long)s0 * 2 + 1]);
    float iy1 = __ldg(&idx[(long)s1 * 2 + 0]);
    float ix1 = __ldg(&idx[(long)s1 * 2 + 1]);

    float fy0 = floorf(iy0), fx0 = floorf(ix0);
    int ay0 = (int)fy0, ax0 = (int)fx0;
    int by0 = (int)ceilf(iy0), bx0 = (int)ceilf(ix0);
    float muy0 = iy0 - fy0, mux0 = ix0 - fx0;

    float fy1 = floorf(iy1), fx1 = floorf(ix1);
    int ay1 = (int)fy1, ax1 = (int)fx1;
    int by1 = (int)ceilf(iy1), bx1 = (int)ceilf(ix1);
    float muy1 = iy1 - fy1, mux1 = ix1 - fx1;

    const float4* base0 = (const float4*)in + (long)b0 * H * W * C4;
    const float4* base1 = (const float4*)in + (long)b1 * H * W * C4;

    // 8 independent gathers, front-batched
    float4 a0 = __ldg(base0 + ((long)ay0 * W + ax0) * C4 + c4);
    float4 q0 = __ldg(base0 + ((long)by0 * W + ax0) * C4 + c4);
    float4 r0 = __ldg(base0 + ((long)ay0 * W + bx0) * C4 + c4);
    float4 d0 = __ldg(base0 + ((long)by0 * W + bx0) * C4 + c4);
    float4 a1 = __ldg(base1 + ((long)ay1 * W + ax1) * C4 + c4);
    float4 q1 = __ldg(base1 + ((long)by1 * W + ax1) * C4 + c4);
    float4 r1 = __ldg(base1 + ((long)ay1 * W + bx1) * C4 + c4);
    float4 d1 = __ldg(base1 + ((long)by1 * W + bx1) * C4 + c4);

    float w00a = (1.0f - muy0) * (1.0f - mux0);
    float w10a = muy0 * (1.0f - mux0);
    float w01a = (1.0f - muy0) * mux0;
    float w11a = muy0 * mux0;

    float w00b = (1.0f - muy1) * (1.0f - mux1);
    float w10b = muy1 * (1.0f - mux1);
    float w01b = (1.0f - muy1) * mux1;
    float w11b = muy1 * mux1;

    float4 o0, o1;
    o0.x = a0.x * w00a + q0.x * w10a + r0.x * w01a + d0.x * w11a;
    o0.y = a0.y * w00a + q0.y * w10a + r0.y * w01a + d0.y * w11a;
    o0.z = a0.z * w00a + q0.z * w10a + r0.z * w01a + d0.z * w11a;
    o0.w = a0.w * w00a + q0.w * w10a + r0.w * w01a + d0.w * w11a;

    o1.x = a1.x * w00b + q1.x * w10b + r1.x * w01b + d1.x * w11b;
    o1.y = a1.y * w00b + q1.y * w10b + r1.y * w01b + d1.y * w11b;
    o1.z = a1.z * w00b + q1.z * w10b + r1.z * w01b + d1.z * w11b;
    o1.w = a1.w * w00b + q1.w * w10b + r1.w * w01b + d1.w * w11b;

    __stcs(((float4*)(out + (long)s0 * C)) + c4, o0);
    __stcs(((float4*)(out + (long)s1 * C)) + c4, o1);
}

extern "C" void kernel_launch(void* const* d_in, const int* in_sizes, int n_in,
                              void* d_out, int out_size)
{
    const float* in_tensor = (const float*)d_in[0];
    const float* indices   = (const float*)d_in[1];
    float* out = (float*)d_out;

    zero_kernel<<<(NBKT + 255) / 256, 256>>>();
    hist_kernel<<<(NPTS + 255) / 256, 256>>>(indices);
    scan_kernel<<<1, 1024>>>();
    scatter_kernel<<<(NPTS + 255) / 256, 256>>>(indices);

    const int threads = 256;
    const long blocks = (TOTAL + threads - 1) / threads;  // 16384
    grid_sample_kernel<<<(unsigned)blocks, threads>>>(in_tensor, indices, out);
}

// round 8
// speedup vs baseline: 1.3185x; 1.3185x over previous
#include <cuda_runtime.h>

// Grid_nd_sample: bilinear interpolation gather.
// in_tensor: (B=16, H=128, W=128, C=256) fp32 (268 MB)
// indices:   (B, P=8192, 2) fp32
// out:       (B, P, C) fp32 (134 MB)
//
// DRAM traffic is at the compulsory floor; perf tracks achieved bandwidth,
// which tracks per-warp front-batched load depth (L1tex queue). 4 points per
// thread = 16 independent 16B gathers. __launch_bounds__(128,4) grants a
// 128-reg budget so ptxas keeps all 16 results live and the loads batched
// (R5 failed because the default reg heuristic clamped to 34 and de-batched).

namespace {
constexpr int B = 16;
constexpr int H = 128;
constexpr int W = 128;
constexpr int C = 256;
constexpr int P = 8192;
constexpr int C4 = C / 4;                       // 64 float4 chunks per point
constexpr long NQUAD = (long)B * P / 4;         // 32768 point-quads
constexpr long TOTAL = NQUAD * C4;              // 2,097,152 threads
}

__global__ __launch_bounds__(128, 4) void grid_sample_kernel(
    const float* __restrict__ in,
    const float* __restrict__ idx,
    float* __restrict__ out)
{
    long i = (long)blockIdx.x * blockDim.x + threadIdx.x;
    if (i >= TOTAL) return;

    int  c4   = (int)(i & (C4 - 1));   // 0..63
    long quad = i >> 6;                // quad id
    long bp0  = quad * 4;              // first point of the quad
    int  b    = (int)(bp0 >> 13);      // P = 8192 = 2^13; quad never spans images

    // Index loads: warp-uniform -> broadcast (8 floats = 4 points)
    float4 iA = __ldg((const float4*)(idx + bp0 * 2));
    float4 iB = __ldg((const float4*)(idx + bp0 * 2) + 1);

    float iy[4] = {iA.x, iA.z, iB.x, iB.z};
    float ix[4] = {iA.y, iA.w, iB.y, iB.w};

    const long imgc4 = (long)b * H * W * C4;
    const float4* base = (const float4*)in + imgc4;

    // Precompute the 16 gather addresses, then issue all 16 loads back-to-back.
    const float4* ap[4];
    const float4* bp[4];
    const float4* cp[4];
    const float4* dp[4];
    float muy[4], mux[4];
#pragma unroll
    for (int p = 0; p < 4; p++) {
        float fy = floorf(iy[p]), fx = floorf(ix[p]);
        int yl = (int)fy,          xl = (int)fx;
        int yh = (int)ceilf(iy[p]), xh = (int)ceilf(ix[p]);
        muy[p] = iy[p] - fy;
        mux[p] = ix[p] - fx;
        ap[p] = base + ((long)yl * W + xl) * C4 + c4;
        bp[p] = base + ((long)yh * W + xl) * C4 + c4;
        cp[p] = base + ((long)yl * W + xh) * C4 + c4;
        dp[p] = base + ((long)yh * W + xh) * C4 + c4;
    }

    float4 v00[4], v10[4], v01[4], v11[4];
#pragma unroll
    for (int p = 0; p < 4; p++) v00[p] = __ldg(ap[p]);
#pragma unroll
    for (int p = 0; p < 4; p++) v10[p] = __ldg(bp[p]);
#pragma unroll
    for (int p = 0; p < 4; p++) v01[p] = __ldg(cp[p]);
#pragma unroll
    for (int p = 0; p < 4; p++) v11[p] = __ldg(dp[p]);

    float4* op = (float4*)(out + bp0 * C) + c4;
#pragma unroll
    for (int p = 0; p < 4; p++) {
        float w00 = (1.0f - muy[p]) * (1.0f - mux[p]);
        float w10 = muy[p] * (1.0f - mux[p]);
        float w01 = (1.0f - muy[p]) * mux[p];
        float w11 = muy[p] * mux[p];

        float4 o;
        o.x = v00[p].x * w00 + v10[p].x * w10 + v01[p].x * w01 + v11[p].x * w11;
        o.y = v00[p].y * w00 + v10[p].y * w10 + v01[p].y * w01 + v11[p].y * w11;
        o.z = v00[p].z * w00 + v10[p].z * w10 + v01[p].z * w01 + v11[p].z * w11;
        o.w = v00[p].w * w00 + v10[p].w * w10 + v01[p].w * w01 + v11[p].w * w11;
        op[(long)p * C4] = o;
    }
}

extern "C" void kernel_launch(void* const* d_in, const int* in_sizes, int n_in,
                              void* d_out, int out_size)
{
    const float* in_tensor = (const float*)d_in[0];
    const float* indices   = (const float*)d_in[1];
    float* out = (float*)d_out;

    const int threads = 128;
    const long blocks = (TOTAL + threads - 1) / threads;  // 16384
    grid_sample_kernel<<<(unsigned)blocks, threads>>>(in_tensor, indices, out);
}

// round 9
// speedup vs baseline: 1.4447x; 1.0957x over previous
#include <cuda_runtime.h>

// Grid_nd_sample: bilinear interpolation gather. (R4-best structure + stcs)
// in_tensor: (B=16, H=128, W=128, C=256) fp32 (268 MB)
// indices:   (B, P=8192, 2) fp32
// out:       (B, P, C) fp32 (134 MB)
//
// Local optimum found empirically: 2 points per thread, 8 front-batched
// independent 16B gathers, 256-thread blocks, high occupancy (~84%).
// Delta this round: streaming (.cs evict-first) output stores so the
// write-once output doesn't evict the L2 lines serving gather reuse.

namespace {
constexpr int B = 16;
constexpr int H = 128;
constexpr int W = 128;
constexpr int C = 256;
constexpr int P = 8192;
constexpr int C4 = C / 4;                       // 64 float4 chunks per point
constexpr long NPAIR = (long)B * P / 2;         // 65536 point-pairs
constexpr long TOTAL = NPAIR * C4;              // 4,194,304 threads
}

__global__ __launch_bounds__(256) void grid_sample_kernel(
    const float* __restrict__ in,
    const float* __restrict__ idx,
    float* __restrict__ out)
{
    long i = (long)blockIdx.x * blockDim.x + threadIdx.x;
    if (i >= TOTAL) return;

    int  c4   = (int)(i & (C4 - 1));   // 0..63
    long pair = i >> 6;                // pair id
    long bp0  = pair * 2;
    long bp1  = bp0 + 1;
    int  b    = (int)(bp0 >> 13);      // P = 8192 = 2^13; pair never spans images

    // Index loads: warp-uniform (all 32 lanes share one pair) -> broadcast
    float4 ii = __ldg((const float4*)(idx + bp0 * 2));  // {y0, x0, y1p, x1p}
    float iy0 = ii.x, ix0 = ii.y, iy1 = ii.z, ix1 = ii.w;

    // Point 0 coords/weights
    float fy0 = floorf(iy0), fx0 = floorf(ix0);
    int ay0 = (int)fy0, ax0 = (int)fx0;
    int by0 = (int)ceilf(iy0), bx0 = (int)ceilf(ix0);
    float muy0 = iy0 - fy0, mux0 = ix0 - fx0;

    // Point 1 coords/weights
    float fy1 = floorf(iy1), fx1 = floorf(ix1);
    int ay1 = (int)fy1, ax1 = (int)fx1;
    int by1 = (int)ceilf(iy1), bx1 = (int)ceilf(ix1);
    float muy1 = iy1 - fy1, mux1 = ix1 - fx1;

    const long img = (long)b * H * W * C;
    const float4* base = (const float4*)(in + img);

    // 8 independent gathers, front-batched for max MLP
    const float4* p0r00 = base + (((long)ay0 * W + ax0) * C4) + c4;
    const float4* p0r10 = base + (((long)by0 * W + ax0) * C4) + c4;
    const float4* p0r01 = base + (((long)ay0 * W + bx0) * C4) + c4;
    const float4* p0r11 = base + (((long)by0 * W + bx0) * C4) + c4;
    const float4* p1r00 = base + (((long)ay1 * W + ax1) * C4) + c4;
    const float4* p1r10 = base + (((long)by1 * W + ax1) * C4) + c4;
    const float4* p1r01 = base + (((long)ay1 * W + bx1) * C4) + c4;
    const float4* p1r11 = base + (((long)by1 * W + bx1) * C4) + c4;

    float4 a0 = __ldg(p0r00);
    float4 b0 = __ldg(p0r10);
    float4 c0 = __ldg(p0r01);
    float4 d0 = __ldg(p0r11);
    float4 a1 = __ldg(p1r00);
    float4 b1 = __ldg(p1r10);
    float4 c1 = __ldg(p1r01);
    float4 d1 = __ldg(p1r11);

    float w00a = (1.0f - muy0) * (1.0f - mux0);
    float w10a = muy0 * (1.0f - mux0);
    float w01a = (1.0f - muy0) * mux0;
    float w11a = muy0 * mux0;

    float w00b = (1.0f - muy1) * (1.0f - mux1);
    float w10b = muy1 * (1.0f - mux1);
    float w01b = (1.0f - muy1) * mux1;
    float w11b = muy1 * mux1;

    float4 o0, o1;
    o0.x = a0.x * w00a + b0.x * w10a + c0.x * w01a + d0.x * w11a;
    o0.y = a0.y * w00a + b0.y * w10a + c0.y * w01a + d0.y * w11a;
    o0.z = a0.z * w00a + b0.z * w10a + c0.z * w01a + d0.z * w11a;
    o0.w = a0.w * w00a + b0.w * w10a + c0.w * w01a + d0.w * w11a;

    o1.x = a1.x * w00b + b1.x * w10b + c1.x * w01b + d1.x * w11b;
    o1.y = a1.y * w00b + b1.y * w10b + c1.y * w01b + d1.y * w11b;
    o1.z = a1.z * w00b + b1.z * w10b + c1.z * w01b + d1.z * w11b;
    o1.w = a1.w * w00b + b1.w * w10b + c1.w * w01b + d1.w * w11b;

    __stcs(((float4*)(out + bp0 * C)) + c4, o0);
    __stcs(((float4*)(out + bp1 * C)) + c4, o1);
}

extern "C" void kernel_launch(void* const* d_in, const int* in_sizes, int n_in,
                              void* d_out, int out_size)
{
    const float* in_tensor = (const float*)d_in[0];
    const float* indices   = (const float*)d_in[1];
    float* out = (float*)d_out;

    const int threads = 256;
    const long blocks = (TOTAL + threads - 1) / threads;  // 16384
    grid_sample_kernel<<<(unsigned)blocks, threads>>>(in_tensor, indices, out);
}